// round 1
// baseline (speedup 1.0000x reference)
#include <cuda_runtime.h>
#include <math.h>

#define NN   50000
#define EE   500000
#define PP   10000
#define FIN  128
#define HH   256
#define ETOT (EE + NN)

// -------- scratch (static device globals; no allocs allowed) --------
__device__ float g_pre [(size_t)NN * HH];   // gemm output / relu output / layer2 agg dest
__device__ float g_post[(size_t)NN * HH];   // layer1 agg dest / layer2 gemm output
__device__ float g_es  [NN];
__device__ float g_ed  [NN];
__device__ float g_m   [NN];
__device__ float g_den [NN];
__device__ float g_elog[ETOT];

// ---------------------------------------------------------------
// SGEMM: C[n,m] = A[n,k] @ B[k,m].  64x64 block tile, 16-deep k tile,
// 256 threads, 4x4 microtile per thread. n arbitrary, k%16==0, m%64==0.
// ---------------------------------------------------------------
__global__ __launch_bounds__(256) void k_sgemm(
    const float* __restrict__ A, const float* __restrict__ B,
    float* __restrict__ C, int n, int k, int m)
{
    __shared__ float As[16][64];
    __shared__ float Bs[16][64];

    const int tid = threadIdx.x;         // 0..255
    const int tr  = tid >> 4;            // 0..15 (row group)
    const int tc  = tid & 15;            // 0..15 (col group)
    const int rowBase = blockIdx.y * 64;
    const int colBase = blockIdx.x * 64;

    float acc[4][4] = {};

    for (int k0 = 0; k0 < k; k0 += 16) {
        // load A tile 64x16 -> As[kk][row]
        #pragma unroll
        for (int i = tid; i < 64 * 16; i += 256) {
            int r  = i >> 4;
            int kk = i & 15;
            int gr = rowBase + r;
            As[kk][r] = (gr < n) ? A[(size_t)gr * k + k0 + kk] : 0.f;
        }
        // load B tile 16x64 -> Bs[kk][c]
        #pragma unroll
        for (int i = tid; i < 16 * 64; i += 256) {
            int kk = i >> 6;
            int c  = i & 63;
            Bs[kk][c] = B[(size_t)(k0 + kk) * m + colBase + c];
        }
        __syncthreads();

        #pragma unroll
        for (int kk = 0; kk < 16; kk++) {
            float4 a = *reinterpret_cast<const float4*>(&As[kk][tr * 4]);
            float4 b = *reinterpret_cast<const float4*>(&Bs[kk][tc * 4]);
            float av[4] = {a.x, a.y, a.z, a.w};
            float bv[4] = {b.x, b.y, b.z, b.w};
            #pragma unroll
            for (int i = 0; i < 4; i++)
                #pragma unroll
                for (int j = 0; j < 4; j++)
                    acc[i][j] += av[i] * bv[j];
        }
        __syncthreads();
    }

    #pragma unroll
    for (int i = 0; i < 4; i++) {
        int gr = rowBase + tr * 4 + i;
        if (gr < n) {
            float4 v = make_float4(acc[i][0], acc[i][1], acc[i][2], acc[i][3]);
            *reinterpret_cast<float4*>(&C[(size_t)gr * m + colBase + tc * 4]) = v;
        }
    }
}

// ---------------------------------------------------------------
// per-node attention dot products: es = h . a_src, ed = h . a_dst
// one warp per node, coalesced row reads
// ---------------------------------------------------------------
__global__ __launch_bounds__(256) void k_esed(
    const float* __restrict__ h, const float* __restrict__ a_s,
    const float* __restrict__ a_d, float* __restrict__ es,
    float* __restrict__ ed, int dim)
{
    int warp = (blockIdx.x * blockDim.x + threadIdx.x) >> 5;
    int lane = threadIdx.x & 31;
    if (warp >= NN) return;
    const float* row = h + (size_t)warp * dim;
    float s = 0.f, d = 0.f;
    for (int j = lane; j < dim; j += 32) {
        float v = row[j];
        s += v * a_s[j];
        d += v * a_d[j];
    }
    #pragma unroll
    for (int o = 16; o; o >>= 1) {
        s += __shfl_xor_sync(0xffffffffu, s, o);
        d += __shfl_xor_sync(0xffffffffu, d, o);
    }
    if (lane == 0) { es[warp] = s; ed[warp] = d; }
}

// ---------------------------------------------------------------
// init node-level softmax state
// ---------------------------------------------------------------
__global__ void k_node_init(float* __restrict__ m, float* __restrict__ den)
{
    int i = blockIdx.x * blockDim.x + threadIdx.x;
    if (i < NN) { m[i] = -INFINITY; den[i] = 0.f; }
}

// fill aggregation buffer with (broadcast) bias — bias fold saves a pass
__global__ void k_fill_bias(float* __restrict__ out, const float* __restrict__ b,
                            int dim_mask, long total)
{
    long i = blockIdx.x * (long)blockDim.x + threadIdx.x;
    if (i < total) out[i] = b[(int)(i & dim_mask)];
}

__device__ __forceinline__ void atomicMaxF(float* addr, float val)
{
    int* ia = (int*)addr;
    int old = *ia;
    while (__int_as_float(old) < val) {
        int assumed = old;
        old = atomicCAS(ia, assumed, __float_as_int(val));
        if (old == assumed) break;
    }
}

// ---------------------------------------------------------------
// edge pass 1: logits + segment max (self-loops appended at e >= EE)
// ---------------------------------------------------------------
__global__ __launch_bounds__(256) void k_edge_logit_max(
    const int* __restrict__ ei, const float* __restrict__ es,
    const float* __restrict__ ed, float* __restrict__ elog,
    float* __restrict__ m)
{
    int e = blockIdx.x * blockDim.x + threadIdx.x;
    if (e >= ETOT) return;
    int s, d;
    if (e < EE) { s = ei[e]; d = ei[EE + e]; }
    else        { s = d = e - EE; }
    float x = es[s] + ed[d];
    float l = (x >= 0.f) ? x : 0.2f * x;   // leaky_relu(0.2)
    elog[e] = l;
    atomicMaxF(&m[d], l);
}

// edge pass 2: p = exp(l - m[dst]); den[dst] += p
__global__ __launch_bounds__(256) void k_edge_exp_sum(
    const int* __restrict__ ei, float* __restrict__ elog,
    const float* __restrict__ m, float* __restrict__ den)
{
    int e = blockIdx.x * blockDim.x + threadIdx.x;
    if (e >= ETOT) return;
    int d = (e < EE) ? ei[EE + e] : (e - EE);
    float p = expf(elog[e] - m[d]);
    elog[e] = p;
    atomicAdd(&den[d], p);
}

// edge pass 3: out[dst] += h[src] * (p / den[dst]) — one warp per edge
__global__ __launch_bounds__(256) void k_edge_aggregate(
    const float* __restrict__ h, const int* __restrict__ ei,
    const float* __restrict__ p, const float* __restrict__ den,
    float* __restrict__ out, int dim)
{
    int warp = (blockIdx.x * blockDim.x + threadIdx.x) >> 5;
    int lane = threadIdx.x & 31;
    if (warp >= ETOT) return;
    int s, d;
    if (warp < EE) { s = ei[warp]; d = ei[EE + warp]; }
    else           { s = d = warp - EE; }
    float alpha = p[warp] / den[d];
    const float* hs = h + (size_t)s * dim;
    float*       od = out + (size_t)d * dim;
    for (int j = lane; j < dim; j += 32)
        atomicAdd(&od[j], hs[j] * alpha);
}

// relu (bias already folded into aggregation init)
__global__ void k_relu(const float* __restrict__ in, float* __restrict__ out, long total)
{
    long i = blockIdx.x * (long)blockDim.x + threadIdx.x;
    if (i < total) out[i] = fmaxf(in[i], 0.f);
}

// ---------------------------------------------------------------
// link predictor: out[p] = sigmoid(h[m0].Wl[0:128] + h[m1].Wl[128:256] + bl)
// one warp per pair
// ---------------------------------------------------------------
__global__ __launch_bounds__(256) void k_link_pred(
    const float* __restrict__ h, const int* __restrict__ mask,
    const float* __restrict__ Wl, const float* __restrict__ bl,
    float* __restrict__ out)
{
    int warp = (blockIdx.x * blockDim.x + threadIdx.x) >> 5;
    int lane = threadIdx.x & 31;
    if (warp >= PP) return;
    int m0 = mask[warp * 2 + 0];
    int m1 = mask[warp * 2 + 1];
    float acc = 0.f;
    #pragma unroll
    for (int j = lane; j < FIN; j += 32) {
        acc += h[(size_t)m0 * FIN + j] * Wl[j];
        acc += h[(size_t)m1 * FIN + j] * Wl[FIN + j];
    }
    #pragma unroll
    for (int o = 16; o; o >>= 1) acc += __shfl_xor_sync(0xffffffffu, acc, o);
    if (lane == 0) out[warp] = 1.f / (1.f + expf(-(acc + bl[0])));
}

// ---------------------------------------------------------------
extern "C" void kernel_launch(void* const* d_in, const int* in_sizes, int n_in,
                              void* d_out, int out_size)
{
    const float* features = (const float*)d_in[0];
    const int*   ei       = (const int*)  d_in[1];
    const int*   mask     = (const int*)  d_in[2];
    const float* W1       = (const float*)d_in[3];
    const float* a_src1   = (const float*)d_in[4];
    const float* a_dst1   = (const float*)d_in[5];
    const float* b1       = (const float*)d_in[6];
    const float* W2       = (const float*)d_in[7];
    const float* a_src2   = (const float*)d_in[8];
    const float* a_dst2   = (const float*)d_in[9];
    const float* b2       = (const float*)d_in[10];
    const float* Wl       = (const float*)d_in[11];
    const float* bl       = (const float*)d_in[12];
    float* out = (float*)d_out;

    float *pre, *post, *es, *ed, *m, *den, *elog;
    cudaGetSymbolAddress((void**)&pre,  g_pre);
    cudaGetSymbolAddress((void**)&post, g_post);
    cudaGetSymbolAddress((void**)&es,   g_es);
    cudaGetSymbolAddress((void**)&ed,   g_ed);
    cudaGetSymbolAddress((void**)&m,    g_m);
    cudaGetSymbolAddress((void**)&den,  g_den);
    cudaGetSymbolAddress((void**)&elog, g_elog);

    const long totH = (long)NN * HH;
    const long totF = (long)NN * FIN;
    const int edgeBlocks = (ETOT + 255) / 256;          // thread-per-edge passes
    const int aggBlocks  = (ETOT * 32 + 255) / 256;     // warp-per-edge pass
    const int nodeWarpBlocks = (NN * 32 + 255) / 256;   // warp-per-node passes

    // ================= layer 1 =================
    {
        dim3 g(HH / 64, (NN + 63) / 64);
        k_sgemm<<<g, 256>>>(features, W1, pre, NN, FIN, HH);
    }
    k_esed<<<nodeWarpBlocks, 256>>>(pre, a_src1, a_dst1, es, ed, HH);
    k_node_init<<<(NN + 255) / 256, 256>>>(m, den);
    k_fill_bias<<<(int)((totH + 255) / 256), 256>>>(post, b1, HH - 1, totH);
    k_edge_logit_max<<<edgeBlocks, 256>>>(ei, es, ed, elog, m);
    k_edge_exp_sum  <<<edgeBlocks, 256>>>(ei, elog, m, den);
    k_edge_aggregate<<<aggBlocks, 256>>>(pre, ei, elog, den, post, HH);
    k_relu<<<(int)((totH + 255) / 256), 256>>>(post, pre, totH);

    // ================= layer 2 =================
    {
        dim3 g(FIN / 64, (NN + 63) / 64);
        k_sgemm<<<g, 256>>>(pre, W2, post, NN, HH, FIN);
    }
    k_esed<<<nodeWarpBlocks, 256>>>(post, a_src2, a_dst2, es, ed, FIN);
    k_node_init<<<(NN + 255) / 256, 256>>>(m, den);
    k_fill_bias<<<(int)((totF + 255) / 256), 256>>>(pre, b2, FIN - 1, totF);
    k_edge_logit_max<<<edgeBlocks, 256>>>(ei, es, ed, elog, m);
    k_edge_exp_sum  <<<edgeBlocks, 256>>>(ei, elog, m, den);
    k_edge_aggregate<<<aggBlocks, 256>>>(post, ei, elog, den, pre, FIN);

    // ================= link predictor =================
    k_link_pred<<<(PP * 32 + 255) / 256, 256>>>(pre, mask, Wl, bl, out);
}

// round 2
// speedup vs baseline: 1.4716x; 1.4716x over previous
#include <cuda_runtime.h>
#include <mma.h>
#include <math.h>

using namespace nvcuda;

#define NN   50000
#define EE   500000
#define PP   10000
#define FIN  128
#define HH   256
#define ETOT (EE + NN)

// -------- scratch (static device globals; no allocs allowed) --------
__device__ float g_pre [(size_t)NN * HH];
__device__ float g_post[(size_t)NN * HH];
__device__ float g_es  [NN];
__device__ float g_ed  [NN];
__device__ float g_den [NN];
__device__ float g_elog[ETOT];

// ---------------------------------------------------------------
// TF32 WMMA GEMM: C[n,m] = A[n,k] @ B[k,m]
// BM=128 BN=64 BK=32, 256 threads (8 warps, 4x2 of 32x32), smem-staged epilogue.
// Requires k%32==0, m%64==0; n arbitrary.
// ---------------------------------------------------------------
#define BM 128
#define BN 64
#define BK 32
#define LDA (BK + 4)   // 36
#define LDB (BN + 4)   // 68

__global__ __launch_bounds__(256) void k_gemm_tf32(
    const float* __restrict__ A, const float* __restrict__ B,
    float* __restrict__ C, int n, int k, int m)
{
    // union: As+Bs (6784 floats) vs Cs (8192 floats) -> 32KB
    __shared__ __align__(16) float smem[BM * BN];
    float* As = smem;                    // [BM][LDA]
    float* Bs = smem + BM * LDA;         // [BK][LDB]
    float* Cs = smem;                    // [BM][BN] (epilogue reuse)

    const int tid = threadIdx.x;
    const int wid = tid >> 5;
    const int wr  = wid & 3;    // 0..3 -> 32-row group
    const int wc  = wid >> 2;   // 0..1 -> 32-col group
    const int rowBase = blockIdx.y * BM;
    const int colBase = blockIdx.x * BN;

    wmma::fragment<wmma::accumulator, 16, 16, 8, float> acc[2][2];
    #pragma unroll
    for (int i = 0; i < 2; i++)
        #pragma unroll
        for (int j = 0; j < 2; j++)
            wmma::fill_fragment(acc[i][j], 0.f);

    for (int k0 = 0; k0 < k; k0 += BK) {
        // load A tile: 128 rows x 8 float4 = 1024 f4; 4 per thread
        #pragma unroll
        for (int i = tid; i < BM * 8; i += 256) {
            int r  = i >> 3;
            int c4 = i & 7;
            int gr = rowBase + r;
            float4 v = make_float4(0.f, 0.f, 0.f, 0.f);
            if (gr < n) v = *reinterpret_cast<const float4*>(&A[(size_t)gr * k + k0 + c4 * 4]);
            *reinterpret_cast<float4*>(&As[r * LDA + c4 * 4]) = v;
        }
        // load B tile: 32 rows x 16 float4 = 512 f4; 2 per thread
        #pragma unroll
        for (int i = tid; i < BK * 16; i += 256) {
            int r  = i >> 4;
            int c4 = i & 15;
            float4 v = *reinterpret_cast<const float4*>(&B[(size_t)(k0 + r) * m + colBase + c4 * 4]);
            *reinterpret_cast<float4*>(&Bs[r * LDB + c4 * 4]) = v;
        }
        __syncthreads();

        #pragma unroll
        for (int kk = 0; kk < BK; kk += 8) {
            wmma::fragment<wmma::matrix_a, 16, 16, 8, wmma::precision::tf32, wmma::row_major> a[2];
            wmma::fragment<wmma::matrix_b, 16, 16, 8, wmma::precision::tf32, wmma::row_major> b[2];
            #pragma unroll
            for (int i = 0; i < 2; i++) {
                wmma::load_matrix_sync(a[i], &As[(wr * 32 + i * 16) * LDA + kk], LDA);
                #pragma unroll
                for (int t = 0; t < a[i].num_elements; t++)
                    a[i].x[t] = wmma::__float_to_tf32(a[i].x[t]);
            }
            #pragma unroll
            for (int j = 0; j < 2; j++) {
                wmma::load_matrix_sync(b[j], &Bs[kk * LDB + wc * 32 + j * 16], LDB);
                #pragma unroll
                for (int t = 0; t < b[j].num_elements; t++)
                    b[j].x[t] = wmma::__float_to_tf32(b[j].x[t]);
            }
            #pragma unroll
            for (int i = 0; i < 2; i++)
                #pragma unroll
                for (int j = 0; j < 2; j++)
                    wmma::mma_sync(acc[i][j], a[i], b[j], acc[i][j]);
        }
        __syncthreads();
    }

    // epilogue: stage through smem (handles n-tail), then guarded float4 copy
    #pragma unroll
    for (int i = 0; i < 2; i++)
        #pragma unroll
        for (int j = 0; j < 2; j++)
            wmma::store_matrix_sync(&Cs[(wr * 32 + i * 16) * BN + wc * 32 + j * 16],
                                    acc[i][j], BN, wmma::mem_row_major);
    __syncthreads();

    #pragma unroll
    for (int i = tid; i < BM * 16; i += 256) {
        int r  = i >> 4;
        int c4 = i & 15;
        int gr = rowBase + r;
        if (gr < n)
            *reinterpret_cast<float4*>(&C[(size_t)gr * m + colBase + c4 * 4]) =
                *reinterpret_cast<const float4*>(&Cs[r * BN + c4 * 4]);
    }
}

// ---------------------------------------------------------------
// per-node attention dots: es = h.a_src, ed = h.a_dst (warp/node, float4)
// ---------------------------------------------------------------
__global__ __launch_bounds__(256) void k_esed(
    const float* __restrict__ h, const float* __restrict__ a_s,
    const float* __restrict__ a_d, float* __restrict__ es,
    float* __restrict__ ed, int dim)
{
    int warp = (blockIdx.x * blockDim.x + threadIdx.x) >> 5;
    int lane = threadIdx.x & 31;
    if (warp >= NN) return;
    const float4* row = reinterpret_cast<const float4*>(h + (size_t)warp * dim);
    const float4* as4 = reinterpret_cast<const float4*>(a_s);
    const float4* ad4 = reinterpret_cast<const float4*>(a_d);
    float s = 0.f, d = 0.f;
    for (int j = lane; j * 4 < dim; j += 32) {
        float4 v = row[j], a = as4[j], b = ad4[j];
        s += v.x * a.x + v.y * a.y + v.z * a.z + v.w * a.w;
        d += v.x * b.x + v.y * b.y + v.z * b.z + v.w * b.w;
    }
    #pragma unroll
    for (int o = 16; o; o >>= 1) {
        s += __shfl_xor_sync(0xffffffffu, s, o);
        d += __shfl_xor_sync(0xffffffffu, d, o);
    }
    if (lane == 0) { es[warp] = s; ed[warp] = d; }
}

// ---------------------------------------------------------------
// init: out = broadcast bias (float4), den = 0
// ---------------------------------------------------------------
__global__ void k_init(float4* __restrict__ out, const float4* __restrict__ b4,
                       int dim4_mask, long total4, float* __restrict__ den)
{
    long i = blockIdx.x * (long)blockDim.x + threadIdx.x;
    if (i < total4) out[i] = b4[(int)(i & dim4_mask)];
    if (i < NN) den[i] = 0.f;
}

// ---------------------------------------------------------------
// fused edge softmax numerator: p = exp(leaky(es[s]+ed[d])); den[d] += p
// (softmax is shift-invariant; logits are O(few), exp cannot overflow)
// ---------------------------------------------------------------
__global__ __launch_bounds__(256) void k_edge_softmax(
    const int* __restrict__ ei, const float* __restrict__ es,
    const float* __restrict__ ed, float* __restrict__ elog,
    float* __restrict__ den)
{
    int e = blockIdx.x * blockDim.x + threadIdx.x;
    if (e >= ETOT) return;
    int s, d;
    if (e < EE) { s = ei[e]; d = ei[EE + e]; }
    else        { s = d = e - EE; }
    float x = es[s] + ed[d];
    float l = (x >= 0.f) ? x : 0.2f * x;
    float p = __expf(l);
    elog[e] = p;
    atomicAdd(&den[d], p);
}

// ---------------------------------------------------------------
// aggregate: out[dst] += h[src] * alpha  — warp/edge, float4 + red.v4
// ---------------------------------------------------------------
__global__ __launch_bounds__(256) void k_edge_aggregate(
    const float* __restrict__ h, const int* __restrict__ ei,
    const float* __restrict__ p, const float* __restrict__ den,
    float* __restrict__ out, int dim)
{
    int warp = (blockIdx.x * blockDim.x + threadIdx.x) >> 5;
    int lane = threadIdx.x & 31;
    if (warp >= ETOT) return;
    int s, d;
    if (warp < EE) { s = ei[warp]; d = ei[EE + warp]; }
    else           { s = d = warp - EE; }
    float alpha = p[warp] / den[d];
    const float4* hs = reinterpret_cast<const float4*>(h + (size_t)s * dim);
    float* od = out + (size_t)d * dim;
    for (int j = lane; j * 4 < dim; j += 32) {
        float4 v = hs[j];
        asm volatile("red.global.add.v4.f32 [%0], {%1, %2, %3, %4};"
                     :: "l"(od + j * 4),
                        "f"(v.x * alpha), "f"(v.y * alpha),
                        "f"(v.z * alpha), "f"(v.w * alpha)
                     : "memory");
    }
}

// relu, float4
__global__ void k_relu(const float4* __restrict__ in, float4* __restrict__ out, long total4)
{
    long i = blockIdx.x * (long)blockDim.x + threadIdx.x;
    if (i < total4) {
        float4 v = in[i];
        out[i] = make_float4(fmaxf(v.x, 0.f), fmaxf(v.y, 0.f),
                             fmaxf(v.z, 0.f), fmaxf(v.w, 0.f));
    }
}

// ---------------------------------------------------------------
// link predictor (warp/pair, float4)
// ---------------------------------------------------------------
__global__ __launch_bounds__(256) void k_link_pred(
    const float* __restrict__ h, const int* __restrict__ mask,
    const float* __restrict__ Wl, const float* __restrict__ bl,
    float* __restrict__ out)
{
    int warp = (blockIdx.x * blockDim.x + threadIdx.x) >> 5;
    int lane = threadIdx.x & 31;
    if (warp >= PP) return;
    int m0 = mask[warp * 2 + 0];
    int m1 = mask[warp * 2 + 1];
    const float4* h0 = reinterpret_cast<const float4*>(h + (size_t)m0 * FIN);
    const float4* h1 = reinterpret_cast<const float4*>(h + (size_t)m1 * FIN);
    const float4* w0 = reinterpret_cast<const float4*>(Wl);
    const float4* w1 = reinterpret_cast<const float4*>(Wl + FIN);
    float4 a = h0[lane], wa = w0[lane];
    float4 b = h1[lane], wb = w1[lane];
    float acc = a.x * wa.x + a.y * wa.y + a.z * wa.z + a.w * wa.w
              + b.x * wb.x + b.y * wb.y + b.z * wb.z + b.w * wb.w;
    #pragma unroll
    for (int o = 16; o; o >>= 1) acc += __shfl_xor_sync(0xffffffffu, acc, o);
    if (lane == 0) out[warp] = 1.f / (1.f + __expf(-(acc + bl[0])));
}

// ---------------------------------------------------------------
extern "C" void kernel_launch(void* const* d_in, const int* in_sizes, int n_in,
                              void* d_out, int out_size)
{
    const float* features = (const float*)d_in[0];
    const int*   ei       = (const int*)  d_in[1];
    const int*   mask     = (const int*)  d_in[2];
    const float* W1       = (const float*)d_in[3];
    const float* a_src1   = (const float*)d_in[4];
    const float* a_dst1   = (const float*)d_in[5];
    const float* b1       = (const float*)d_in[6];
    const float* W2       = (const float*)d_in[7];
    const float* a_src2   = (const float*)d_in[8];
    const float* a_dst2   = (const float*)d_in[9];
    const float* b2       = (const float*)d_in[10];
    const float* Wl       = (const float*)d_in[11];
    const float* bl       = (const float*)d_in[12];
    float* out = (float*)d_out;

    float *pre, *post, *es, *ed, *den, *elog;
    cudaGetSymbolAddress((void**)&pre,  g_pre);
    cudaGetSymbolAddress((void**)&post, g_post);
    cudaGetSymbolAddress((void**)&es,   g_es);
    cudaGetSymbolAddress((void**)&ed,   g_ed);
    cudaGetSymbolAddress((void**)&den,  g_den);
    cudaGetSymbolAddress((void**)&elog, g_elog);

    const long totH4 = (long)NN * HH / 4;
    const long totF4 = (long)NN * FIN / 4;
    const int edgeBlocks     = (ETOT + 255) / 256;
    const int aggBlocks      = (int)(((long)ETOT * 32 + 255) / 256);
    const int nodeWarpBlocks = (NN * 32 + 255) / 256;

    // ================= layer 1 =================
    {
        dim3 g(HH / BN, (NN + BM - 1) / BM);
        k_gemm_tf32<<<g, 256>>>(features, W1, pre, NN, FIN, HH);
    }
    k_esed<<<nodeWarpBlocks, 256>>>(pre, a_src1, a_dst1, es, ed, HH);
    k_init<<<(int)((totH4 + 255) / 256), 256>>>((float4*)post, (const float4*)b1, HH / 4 - 1, totH4, den);
    k_edge_softmax<<<edgeBlocks, 256>>>(ei, es, ed, elog, den);
    k_edge_aggregate<<<aggBlocks, 256>>>(pre, ei, elog, den, post, HH);
    k_relu<<<(int)((totH4 + 255) / 256), 256>>>((const float4*)post, (float4*)pre, totH4);

    // ================= layer 2 =================
    {
        dim3 g(FIN / BN, (NN + BM - 1) / BM);
        k_gemm_tf32<<<g, 256>>>(pre, W2, post, NN, HH, FIN);
    }
    k_esed<<<nodeWarpBlocks, 256>>>(post, a_src2, a_dst2, es, ed, FIN);
    k_init<<<(int)((totF4 + 255) / 256), 256>>>((float4*)pre, (const float4*)b2, FIN / 4 - 1, totF4, den);
    k_edge_softmax<<<edgeBlocks, 256>>>(ei, es, ed, elog, den);
    k_edge_aggregate<<<aggBlocks, 256>>>(post, ei, elog, den, pre, FIN);

    // ================= link predictor =================
    k_link_pred<<<(PP * 32 + 255) / 256, 256>>>(pre, mask, Wl, bl, out);
}

// round 3
// speedup vs baseline: 2.3980x; 1.6295x over previous
#include <cuda_runtime.h>
#include <cuda_fp16.h>
#include <mma.h>
#include <math.h>

using namespace nvcuda;

#define NN   50000
#define EE   500000
#define PP   10000
#define FIN  128
#define HH   256
#define ETOT (EE + NN)

// -------- scratch (static device globals; no allocs allowed) --------
__device__ float  g_pre [(size_t)NN * HH];
__device__ float  g_post[(size_t)NN * HH];
__device__ __half g_h16 [(size_t)NN * HH];
__device__ float  g_es  [NN];
__device__ float  g_ed  [NN];
__device__ int    g_deg [NN];
__device__ int    g_pref[NN];
__device__ int    g_bsum[64];
__device__ int    g_rowp[NN + 1];
__device__ int    g_curs[NN];
__device__ int    g_csrc[ETOT];

// ---------------------------------------------------------------
// TF32 WMMA GEMM: C[n,m] = A[n,k] @ B[k,m], plus fp16 shadow copy C16.
// BM=128 BN=64 BK=32, 256 threads.
// ---------------------------------------------------------------
#define BM 128
#define BN 64
#define BK 32
#define LDA (BK + 4)
#define LDB (BN + 4)

__global__ __launch_bounds__(256) void k_gemm_tf32(
    const float* __restrict__ A, const float* __restrict__ B,
    float* __restrict__ C, __half* __restrict__ C16, int n, int k, int m)
{
    __shared__ __align__(16) float smem[BM * BN];
    float* As = smem;
    float* Bs = smem + BM * LDA;
    float* Cs = smem;

    const int tid = threadIdx.x;
    const int wid = tid >> 5;
    const int wr  = wid & 3;
    const int wc  = wid >> 2;
    const int rowBase = blockIdx.y * BM;
    const int colBase = blockIdx.x * BN;

    wmma::fragment<wmma::accumulator, 16, 16, 8, float> acc[2][2];
    #pragma unroll
    for (int i = 0; i < 2; i++)
        #pragma unroll
        for (int j = 0; j < 2; j++)
            wmma::fill_fragment(acc[i][j], 0.f);

    for (int k0 = 0; k0 < k; k0 += BK) {
        #pragma unroll
        for (int i = tid; i < BM * 8; i += 256) {
            int r  = i >> 3;
            int c4 = i & 7;
            int gr = rowBase + r;
            float4 v = make_float4(0.f, 0.f, 0.f, 0.f);
            if (gr < n) v = *reinterpret_cast<const float4*>(&A[(size_t)gr * k + k0 + c4 * 4]);
            *reinterpret_cast<float4*>(&As[r * LDA + c4 * 4]) = v;
        }
        #pragma unroll
        for (int i = tid; i < BK * 16; i += 256) {
            int r  = i >> 4;
            int c4 = i & 15;
            float4 v = *reinterpret_cast<const float4*>(&B[(size_t)(k0 + r) * m + colBase + c4 * 4]);
            *reinterpret_cast<float4*>(&Bs[r * LDB + c4 * 4]) = v;
        }
        __syncthreads();

        #pragma unroll
        for (int kk = 0; kk < BK; kk += 8) {
            wmma::fragment<wmma::matrix_a, 16, 16, 8, wmma::precision::tf32, wmma::row_major> a[2];
            wmma::fragment<wmma::matrix_b, 16, 16, 8, wmma::precision::tf32, wmma::row_major> b[2];
            #pragma unroll
            for (int i = 0; i < 2; i++) {
                wmma::load_matrix_sync(a[i], &As[(wr * 32 + i * 16) * LDA + kk], LDA);
                #pragma unroll
                for (int t = 0; t < a[i].num_elements; t++)
                    a[i].x[t] = wmma::__float_to_tf32(a[i].x[t]);
            }
            #pragma unroll
            for (int j = 0; j < 2; j++) {
                wmma::load_matrix_sync(b[j], &Bs[kk * LDB + wc * 32 + j * 16], LDB);
                #pragma unroll
                for (int t = 0; t < b[j].num_elements; t++)
                    b[j].x[t] = wmma::__float_to_tf32(b[j].x[t]);
            }
            #pragma unroll
            for (int i = 0; i < 2; i++)
                #pragma unroll
                for (int j = 0; j < 2; j++)
                    wmma::mma_sync(acc[i][j], a[i], b[j], acc[i][j]);
        }
        __syncthreads();
    }

    #pragma unroll
    for (int i = 0; i < 2; i++)
        #pragma unroll
        for (int j = 0; j < 2; j++)
            wmma::store_matrix_sync(&Cs[(wr * 32 + i * 16) * BN + wc * 32 + j * 16],
                                    acc[i][j], BN, wmma::mem_row_major);
    __syncthreads();

    #pragma unroll
    for (int i = tid; i < BM * 16; i += 256) {
        int r  = i >> 4;
        int c4 = i & 15;
        int gr = rowBase + r;
        if (gr < n) {
            float4 v = *reinterpret_cast<const float4*>(&Cs[r * BN + c4 * 4]);
            *reinterpret_cast<float4*>(&C[(size_t)gr * m + colBase + c4 * 4]) = v;
            __half2 h0 = __floats2half2_rn(v.x, v.y);
            __half2 h1 = __floats2half2_rn(v.z, v.w);
            *reinterpret_cast<__half2*>(&C16[(size_t)gr * m + colBase + c4 * 4 + 0]) = h0;
            *reinterpret_cast<__half2*>(&C16[(size_t)gr * m + colBase + c4 * 4 + 2]) = h1;
        }
    }
}

// ---------------------------------------------------------------
// CSR build: deg-zero, histogram, 2-level exclusive scan, scatter
// ---------------------------------------------------------------
__device__ __forceinline__ int edge_src(const int* ei, int e) { return (e < EE) ? ei[e]      : e - EE; }
__device__ __forceinline__ int edge_dst(const int* ei, int e) { return (e < EE) ? ei[EE + e] : e - EE; }

__global__ void k_zero_deg(int* __restrict__ deg)
{
    int i = blockIdx.x * blockDim.x + threadIdx.x;
    if (i < NN) deg[i] = 0;
}

__global__ __launch_bounds__(256) void k_hist(const int* __restrict__ ei, int* __restrict__ deg)
{
    int e = blockIdx.x * blockDim.x + threadIdx.x;
    if (e < ETOT) atomicAdd(&deg[edge_dst(ei, e)], 1);
}

#define SB 1024   // elements per scan block (256 thr x 4)
__global__ __launch_bounds__(256) void k_scan1(const int* __restrict__ deg,
    int* __restrict__ pre, int* __restrict__ bsum, int n)
{
    __shared__ int sd[256];
    int tid  = threadIdx.x;
    int base = blockIdx.x * SB + tid * 4;
    int v0 = (base + 0 < n) ? deg[base + 0] : 0;
    int v1 = (base + 1 < n) ? deg[base + 1] : 0;
    int v2 = (base + 2 < n) ? deg[base + 2] : 0;
    int v3 = (base + 3 < n) ? deg[base + 3] : 0;
    int tsum = v0 + v1 + v2 + v3;
    sd[tid] = tsum;
    __syncthreads();
    for (int off = 1; off < 256; off <<= 1) {
        int t = (tid >= off) ? sd[tid - off] : 0;
        __syncthreads();
        sd[tid] += t;
        __syncthreads();
    }
    int r = sd[tid] - tsum;   // exclusive prefix within block
    if (tid == 255) bsum[blockIdx.x] = sd[255];
    if (base + 0 < n) { pre[base + 0] = r; r += v0; }
    if (base + 1 < n) { pre[base + 1] = r; r += v1; }
    if (base + 2 < n) { pre[base + 2] = r; r += v2; }
    if (base + 3 < n) { pre[base + 3] = r; r += v3; }
}

__global__ void k_scan2(int* __restrict__ bsum, int nb)
{
    __shared__ int s[64];
    int tid = threadIdx.x;
    if (tid < nb) s[tid] = bsum[tid];
    __syncthreads();
    if (tid == 0) {
        int run = 0;
        for (int i = 0; i < nb; i++) { int t = s[i]; s[i] = run; run += t; }
    }
    __syncthreads();
    if (tid < nb) bsum[tid] = s[tid];
}

__global__ void k_scan3(const int* __restrict__ pre, const int* __restrict__ bsum,
                        int* __restrict__ rowp, int* __restrict__ curs, int n)
{
    int i = blockIdx.x * blockDim.x + threadIdx.x;
    if (i < n) {
        int v = pre[i] + bsum[i / SB];
        rowp[i] = v;
        curs[i] = v;
    }
    if (i == 0) rowp[n] = ETOT;
}

__global__ __launch_bounds__(256) void k_scatter(const int* __restrict__ ei,
    int* __restrict__ curs, int* __restrict__ csrc)
{
    int e = blockIdx.x * blockDim.x + threadIdx.x;
    if (e >= ETOT) return;
    int d = edge_dst(ei, e);
    int pos = atomicAdd(&curs[d], 1);
    csrc[pos] = edge_src(ei, e);
}

// ---------------------------------------------------------------
// per-node attention dots (warp/node, float4)
// ---------------------------------------------------------------
__global__ __launch_bounds__(256) void k_esed(
    const float* __restrict__ h, const float* __restrict__ a_s,
    const float* __restrict__ a_d, float* __restrict__ es,
    float* __restrict__ ed, int dim)
{
    int warp = (blockIdx.x * blockDim.x + threadIdx.x) >> 5;
    int lane = threadIdx.x & 31;
    if (warp >= NN) return;
    const float4* row = reinterpret_cast<const float4*>(h + (size_t)warp * dim);
    const float4* as4 = reinterpret_cast<const float4*>(a_s);
    const float4* ad4 = reinterpret_cast<const float4*>(a_d);
    float s = 0.f, d = 0.f;
    for (int j = lane; j * 4 < dim; j += 32) {
        float4 v = row[j], a = as4[j], b = ad4[j];
        s += v.x * a.x + v.y * a.y + v.z * a.z + v.w * a.w;
        d += v.x * b.x + v.y * b.y + v.z * b.z + v.w * b.w;
    }
    #pragma unroll
    for (int o = 16; o; o >>= 1) {
        s += __shfl_xor_sync(0xffffffffu, s, o);
        d += __shfl_xor_sync(0xffffffffu, d, o);
    }
    if (lane == 0) { es[warp] = s; ed[warp] = d; }
}

// ---------------------------------------------------------------
// fused GAT softmax + aggregate: warp per dst node, CSR edges.
// den computed in-warp (softmax shift dropped: logits O(1), no overflow).
// Gathers fp16 h rows, accumulates fp32, writes bias(+relu) once.
// ---------------------------------------------------------------
template<int DIM, bool RELU>
__global__ __launch_bounds__(256) void k_gat_agg(
    const __half* __restrict__ h16, const float* __restrict__ es,
    const float* __restrict__ ed, const int* __restrict__ rowp,
    const int* __restrict__ csrc, const float* __restrict__ bias,
    float* __restrict__ out)
{
    constexpr int NH = DIM / 32;          // halves per lane (8 or 4)
    int w    = (blockIdx.x * blockDim.x + threadIdx.x) >> 5;
    int lane = threadIdx.x & 31;
    if (w >= NN) return;

    int start = rowp[w];
    int end   = rowp[w + 1];
    float edv = ed[w];

    // pass 1: denominator
    float den = 0.f;
    for (int base = start; base < end; base += 32) {
        int e = base + lane;
        float p = 0.f;
        if (e < end) {
            float x = es[csrc[e]] + edv;
            x = (x >= 0.f) ? x : 0.2f * x;
            p = __expf(x);
        }
        den += p;
    }
    #pragma unroll
    for (int o = 16; o; o >>= 1) den += __shfl_xor_sync(0xffffffffu, den, o);
    float inv = 1.f / den;

    // pass 2: weighted feature accumulation
    float acc[NH] = {};
    for (int base = start; base < end; base += 32) {
        int e = base + lane;
        int sl = 0;
        float p = 0.f;
        if (e < end) {
            sl = csrc[e];
            float x = es[sl] + edv;
            x = (x >= 0.f) ? x : 0.2f * x;
            p = __expf(x);
        }
        int cnt = min(32, end - base);
        for (int j = 0; j < cnt; j++) {
            int   s = __shfl_sync(0xffffffffu, sl, j);
            float a = __shfl_sync(0xffffffffu, p,  j) * inv;
            const __half* hp = h16 + (size_t)s * DIM + lane * NH;
            if (NH == 8) {
                float4 raw = *reinterpret_cast<const float4*>(hp);
                const __half2* hh = reinterpret_cast<const __half2*>(&raw);
                #pragma unroll
                for (int t = 0; t < 4; t++) {
                    float2 f = __half22float2(hh[t]);
                    acc[t * 2 + 0] += a * f.x;
                    acc[t * 2 + 1] += a * f.y;
                }
            } else {
                float2 raw = *reinterpret_cast<const float2*>(hp);
                const __half2* hh = reinterpret_cast<const __half2*>(&raw);
                #pragma unroll
                for (int t = 0; t < 2; t++) {
                    float2 f = __half22float2(hh[t]);
                    acc[t * 2 + 0] += a * f.x;
                    acc[t * 2 + 1] += a * f.y;
                }
            }
        }
    }

    // epilogue: bias (+relu), single vectorized write
    float* op = out + (size_t)w * DIM + lane * NH;
    const float* bp = bias + lane * NH;
    #pragma unroll
    for (int t4 = 0; t4 < NH / 4; t4++) {
        float4 b = *reinterpret_cast<const float4*>(bp + t4 * 4);
        float4 v = make_float4(acc[t4 * 4 + 0] + b.x, acc[t4 * 4 + 1] + b.y,
                               acc[t4 * 4 + 2] + b.z, acc[t4 * 4 + 3] + b.w);
        if (RELU) {
            v.x = fmaxf(v.x, 0.f); v.y = fmaxf(v.y, 0.f);
            v.z = fmaxf(v.z, 0.f); v.w = fmaxf(v.w, 0.f);
        }
        *reinterpret_cast<float4*>(op + t4 * 4) = v;
    }
}

// ---------------------------------------------------------------
// link predictor (warp/pair, float4)
// ---------------------------------------------------------------
__global__ __launch_bounds__(256) void k_link_pred(
    const float* __restrict__ h, const int* __restrict__ mask,
    const float* __restrict__ Wl, const float* __restrict__ bl,
    float* __restrict__ out)
{
    int warp = (blockIdx.x * blockDim.x + threadIdx.x) >> 5;
    int lane = threadIdx.x & 31;
    if (warp >= PP) return;
    int m0 = mask[warp * 2 + 0];
    int m1 = mask[warp * 2 + 1];
    const float4* h0 = reinterpret_cast<const float4*>(h + (size_t)m0 * FIN);
    const float4* h1 = reinterpret_cast<const float4*>(h + (size_t)m1 * FIN);
    const float4* w0 = reinterpret_cast<const float4*>(Wl);
    const float4* w1 = reinterpret_cast<const float4*>(Wl + FIN);
    float4 a = h0[lane], wa = w0[lane];
    float4 b = h1[lane], wb = w1[lane];
    float acc = a.x * wa.x + a.y * wa.y + a.z * wa.z + a.w * wa.w
              + b.x * wb.x + b.y * wb.y + b.z * wb.z + b.w * wb.w;
    #pragma unroll
    for (int o = 16; o; o >>= 1) acc += __shfl_xor_sync(0xffffffffu, acc, o);
    if (lane == 0) out[warp] = 1.f / (1.f + __expf(-(acc + bl[0])));
}

// ---------------------------------------------------------------
extern "C" void kernel_launch(void* const* d_in, const int* in_sizes, int n_in,
                              void* d_out, int out_size)
{
    const float* features = (const float*)d_in[0];
    const int*   ei       = (const int*)  d_in[1];
    const int*   mask     = (const int*)  d_in[2];
    const float* W1       = (const float*)d_in[3];
    const float* a_src1   = (const float*)d_in[4];
    const float* a_dst1   = (const float*)d_in[5];
    const float* b1       = (const float*)d_in[6];
    const float* W2       = (const float*)d_in[7];
    const float* a_src2   = (const float*)d_in[8];
    const float* a_dst2   = (const float*)d_in[9];
    const float* b2       = (const float*)d_in[10];
    const float* Wl       = (const float*)d_in[11];
    const float* bl       = (const float*)d_in[12];
    float* out = (float*)d_out;

    float  *pre, *post, *es, *ed;
    __half *h16;
    int *deg, *prefix, *bsum, *rowp, *curs, *csrc;
    cudaGetSymbolAddress((void**)&pre,    g_pre);
    cudaGetSymbolAddress((void**)&post,   g_post);
    cudaGetSymbolAddress((void**)&h16,    g_h16);
    cudaGetSymbolAddress((void**)&es,     g_es);
    cudaGetSymbolAddress((void**)&ed,     g_ed);
    cudaGetSymbolAddress((void**)&deg,    g_deg);
    cudaGetSymbolAddress((void**)&prefix, g_pref);
    cudaGetSymbolAddress((void**)&bsum,   g_bsum);
    cudaGetSymbolAddress((void**)&rowp,   g_rowp);
    cudaGetSymbolAddress((void**)&curs,   g_curs);
    cudaGetSymbolAddress((void**)&csrc,   g_csrc);

    const int edgeBlocks     = (ETOT + 255) / 256;
    const int nodeWarpBlocks = (NN * 32 + 255) / 256;
    const int scanBlocks     = (NN + SB - 1) / SB;

    // ---- CSR build (reused by both layers) ----
    k_zero_deg<<<(NN + 255) / 256, 256>>>(deg);
    k_hist   <<<edgeBlocks, 256>>>(ei, deg);
    k_scan1  <<<scanBlocks, 256>>>(deg, prefix, bsum, NN);
    k_scan2  <<<1, 64>>>(bsum, scanBlocks);
    k_scan3  <<<(NN + 255) / 256, 256>>>(prefix, bsum, rowp, curs, NN);
    k_scatter<<<edgeBlocks, 256>>>(ei, curs, csrc);

    // ---- layer 1 ----
    {
        dim3 g(HH / BN, (NN + BM - 1) / BM);
        k_gemm_tf32<<<g, 256>>>(features, W1, pre, h16, NN, FIN, HH);
    }
    k_esed<<<nodeWarpBlocks, 256>>>(pre, a_src1, a_dst1, es, ed, HH);
    k_gat_agg<HH, true><<<nodeWarpBlocks, 256>>>(h16, es, ed, rowp, csrc, b1, post);

    // ---- layer 2 ----
    {
        dim3 g(FIN / BN, (NN + BM - 1) / BM);
        k_gemm_tf32<<<g, 256>>>(post, W2, pre, h16, NN, HH, FIN);
    }
    k_esed<<<nodeWarpBlocks, 256>>>(pre, a_src2, a_dst2, es, ed, FIN);
    k_gat_agg<FIN, false><<<nodeWarpBlocks, 256>>>(h16, es, ed, rowp, csrc, b2, post);

    // ---- link predictor ----
    k_link_pred<<<(PP * 32 + 255) / 256, 256>>>(post, mask, Wl, bl, out);
}

// round 4
// speedup vs baseline: 2.5788x; 1.0754x over previous
#include <cuda_runtime.h>
#include <cuda_fp16.h>
#include <mma.h>
#include <math.h>

using namespace nvcuda;

#define NN   50000
#define EE   500000
#define PP   10000
#define FIN  128
#define HH   256
#define ETOT (EE + NN)

// -------- scratch (static device globals; no allocs allowed) --------
__device__ __half g_h1  [(size_t)NN * HH];   // gemm1 out (fp16)
__device__ __half g_r16 [(size_t)NN * HH];   // relu(agg1) (fp16) = gemm2 input
__device__ __half g_h2  [(size_t)NN * FIN];  // gemm2 out (fp16)
__device__ float  g_post[(size_t)NN * FIN];  // agg2 out (fp32, linkpred input)
__device__ float  g_es  [NN];
__device__ float  g_ed  [NN];
__device__ int    g_deg [NN];
__device__ int    g_rowp[NN + 1];
__device__ int    g_curs[NN];
__device__ int    g_csrc[ETOT];

// ---------------------------------------------------------------
// FP16 WMMA GEMM: C16[n,m] = A[n,k] @ B[k,m]  (fp32 accumulate)
// A is fp32 or fp16 (template); B is fp32, converted while staging.
// BM=128 BN=64 BK=64, 256 threads (8 warps, 4x2 of 32x32).
// ---------------------------------------------------------------
#define BM 128
#define BN 64
#define BK 64
#define LDA (BK + 8)   // halves
#define LDB (BN + 8)   // halves

template<bool A_FP32>
__global__ __launch_bounds__(256) void k_gemm_f16(
    const void* __restrict__ Av, const float* __restrict__ B,
    __half* __restrict__ C, int n, int k, int m)
{
    __shared__ __align__(16) unsigned char smem_raw[BM * BN * 4]; // 32KB
    __half* As = reinterpret_cast<__half*>(smem_raw);
    __half* Bs = As + BM * LDA;
    float*  Cs = reinterpret_cast<float*>(smem_raw);

    const int tid = threadIdx.x;
    const int wid = tid >> 5;
    const int wr  = wid & 3;
    const int wc  = wid >> 2;
    const int rowBase = blockIdx.y * BM;
    const int colBase = blockIdx.x * BN;

    wmma::fragment<wmma::accumulator, 16, 16, 16, float> acc[2][2];
    #pragma unroll
    for (int i = 0; i < 2; i++)
        #pragma unroll
        for (int j = 0; j < 2; j++)
            wmma::fill_fragment(acc[i][j], 0.f);

    for (int k0 = 0; k0 < k; k0 += BK) {
        // ---- stage A tile (BM x BK halves), 8-half chunks, 4/thread ----
        #pragma unroll
        for (int i = tid; i < BM * (BK / 8); i += 256) {
            int r  = i >> 3;
            int c8 = i & 7;
            int gr = rowBase + r;
            uint4 out = make_uint4(0, 0, 0, 0);
            if (gr < n) {
                if (A_FP32) {
                    const float4* p = reinterpret_cast<const float4*>(
                        (const float*)Av + (size_t)gr * k + k0 + c8 * 8);
                    float4 u0 = p[0], u1 = p[1];
                    __half2 h0 = __floats2half2_rn(u0.x, u0.y);
                    __half2 h1 = __floats2half2_rn(u0.z, u0.w);
                    __half2 h2 = __floats2half2_rn(u1.x, u1.y);
                    __half2 h3 = __floats2half2_rn(u1.z, u1.w);
                    out.x = *(unsigned*)&h0; out.y = *(unsigned*)&h1;
                    out.z = *(unsigned*)&h2; out.w = *(unsigned*)&h3;
                } else {
                    out = *reinterpret_cast<const uint4*>(
                        (const __half*)Av + (size_t)gr * k + k0 + c8 * 8);
                }
            }
            *reinterpret_cast<uint4*>(&As[r * LDA + c8 * 8]) = out;
        }
        // ---- stage B tile (BK x BN halves), convert fp32->fp16, 2/thread ----
        #pragma unroll
        for (int i = tid; i < BK * (BN / 8); i += 256) {
            int r  = i >> 3;
            int c8 = i & 7;
            const float4* p = reinterpret_cast<const float4*>(
                &B[(size_t)(k0 + r) * m + colBase + c8 * 8]);
            float4 u0 = p[0], u1 = p[1];
            __half2 h0 = __floats2half2_rn(u0.x, u0.y);
            __half2 h1 = __floats2half2_rn(u0.z, u0.w);
            __half2 h2 = __floats2half2_rn(u1.x, u1.y);
            __half2 h3 = __floats2half2_rn(u1.z, u1.w);
            uint4 out;
            out.x = *(unsigned*)&h0; out.y = *(unsigned*)&h1;
            out.z = *(unsigned*)&h2; out.w = *(unsigned*)&h3;
            *reinterpret_cast<uint4*>(&Bs[r * LDB + c8 * 8]) = out;
        }
        __syncthreads();

        #pragma unroll
        for (int kk = 0; kk < BK; kk += 16) {
            wmma::fragment<wmma::matrix_a, 16, 16, 16, __half, wmma::row_major> a[2];
            wmma::fragment<wmma::matrix_b, 16, 16, 16, __half, wmma::row_major> b[2];
            #pragma unroll
            for (int i = 0; i < 2; i++)
                wmma::load_matrix_sync(a[i], &As[(wr * 32 + i * 16) * LDA + kk], LDA);
            #pragma unroll
            for (int j = 0; j < 2; j++)
                wmma::load_matrix_sync(b[j], &Bs[kk * LDB + wc * 32 + j * 16], LDB);
            #pragma unroll
            for (int i = 0; i < 2; i++)
                #pragma unroll
                for (int j = 0; j < 2; j++)
                    wmma::mma_sync(acc[i][j], a[i], b[j], acc[i][j]);
        }
        __syncthreads();
    }

    // ---- epilogue: stage fp32 in smem, emit fp16 ----
    #pragma unroll
    for (int i = 0; i < 2; i++)
        #pragma unroll
        for (int j = 0; j < 2; j++)
            wmma::store_matrix_sync(&Cs[(wr * 32 + i * 16) * BN + wc * 32 + j * 16],
                                    acc[i][j], BN, wmma::mem_row_major);
    __syncthreads();

    #pragma unroll
    for (int i = tid; i < BM * (BN / 8); i += 256) {
        int r  = i >> 3;
        int c8 = i & 7;
        int gr = rowBase + r;
        if (gr < n) {
            const float4* p = reinterpret_cast<const float4*>(&Cs[r * BN + c8 * 8]);
            float4 u0 = p[0], u1 = p[1];
            __half2 h0 = __floats2half2_rn(u0.x, u0.y);
            __half2 h1 = __floats2half2_rn(u0.z, u0.w);
            __half2 h2 = __floats2half2_rn(u1.x, u1.y);
            __half2 h3 = __floats2half2_rn(u1.z, u1.w);
            uint4 out;
            out.x = *(unsigned*)&h0; out.y = *(unsigned*)&h1;
            out.z = *(unsigned*)&h2; out.w = *(unsigned*)&h3;
            *reinterpret_cast<uint4*>(&C[(size_t)gr * m + colBase + c8 * 8]) = out;
        }
    }
}

// ---------------------------------------------------------------
// CSR build
// ---------------------------------------------------------------
__device__ __forceinline__ int edge_src(const int* ei, int e) { return (e < EE) ? ei[e]      : e - EE; }
__device__ __forceinline__ int edge_dst(const int* ei, int e) { return (e < EE) ? ei[EE + e] : e - EE; }

__global__ void k_zero_deg(int* __restrict__ deg)
{
    int i = blockIdx.x * blockDim.x + threadIdx.x;
    if (i < NN) deg[i] = 0;
}

__global__ __launch_bounds__(256) void k_hist(const int* __restrict__ ei, int* __restrict__ deg)
{
    int e = blockIdx.x * blockDim.x + threadIdx.x;
    if (e < ETOT) atomicAdd(&deg[edge_dst(ei, e)], 1);
}

#define SCAN_T 1024
__global__ __launch_bounds__(SCAN_T) void k_scan_fused(
    const int* __restrict__ deg, int* __restrict__ rowp, int* __restrict__ curs)
{
    __shared__ int sd[SCAN_T];
    const int tid   = threadIdx.x;
    const int chunk = (NN + SCAN_T - 1) / SCAN_T;
    const int base  = tid * chunk;
    int sum = 0;
    for (int j = 0; j < chunk; j++) {
        int i = base + j;
        if (i < NN) sum += deg[i];
    }
    sd[tid] = sum;
    __syncthreads();
    for (int off = 1; off < SCAN_T; off <<= 1) {
        int t = (tid >= off) ? sd[tid - off] : 0;
        __syncthreads();
        sd[tid] += t;
        __syncthreads();
    }
    int run = sd[tid] - sum;   // exclusive prefix
    for (int j = 0; j < chunk; j++) {
        int i = base + j;
        if (i < NN) {
            rowp[i] = run;
            curs[i] = run;
            run += deg[i];
        }
    }
    if (tid == 0) rowp[NN] = ETOT;
}

__global__ __launch_bounds__(256) void k_scatter(const int* __restrict__ ei,
    int* __restrict__ curs, int* __restrict__ csrc)
{
    int e = blockIdx.x * blockDim.x + threadIdx.x;
    if (e >= ETOT) return;
    int d = edge_dst(ei, e);
    int pos = atomicAdd(&curs[d], 1);
    csrc[pos] = edge_src(ei, e);
}

// ---------------------------------------------------------------
// attention dots on fp16 h: es = h.a_src, ed = h.a_dst (warp/node)
// ---------------------------------------------------------------
__global__ __launch_bounds__(256) void k_esed16(
    const __half2* __restrict__ h, const float2* __restrict__ a_s2,
    const float2* __restrict__ a_d2, float* __restrict__ es,
    float* __restrict__ ed, int dim2)
{
    int w    = (blockIdx.x * blockDim.x + threadIdx.x) >> 5;
    int lane = threadIdx.x & 31;
    if (w >= NN) return;
    const __half2* row = h + (size_t)w * dim2;
    float s = 0.f, d = 0.f;
    for (int j = lane; j < dim2; j += 32) {
        float2 v = __half22float2(row[j]);
        float2 a = a_s2[j], b = a_d2[j];
        s += v.x * a.x + v.y * a.y;
        d += v.x * b.x + v.y * b.y;
    }
    #pragma unroll
    for (int o = 16; o; o >>= 1) {
        s += __shfl_xor_sync(0xffffffffu, s, o);
        d += __shfl_xor_sync(0xffffffffu, d, o);
    }
    if (lane == 0) { es[w] = s; ed[w] = d; }
}

// ---------------------------------------------------------------
// fused GAT softmax + aggregate: warp per dst node, CSR edges.
// fp16 gathers, fp32 accumulate, bias(+relu) fused; out fp16 or fp32.
// ---------------------------------------------------------------
template<int DIM, bool RELU, bool OUT16>
__global__ __launch_bounds__(256) void k_gat_agg(
    const __half* __restrict__ h16, const float* __restrict__ es,
    const float* __restrict__ ed, const int* __restrict__ rowp,
    const int* __restrict__ csrc, const float* __restrict__ bias,
    float* __restrict__ outF, __half* __restrict__ outH)
{
    constexpr int NH = DIM / 32;          // halves per lane (8 or 4)
    int w    = (blockIdx.x * blockDim.x + threadIdx.x) >> 5;
    int lane = threadIdx.x & 31;
    if (w >= NN) return;

    int start = rowp[w];
    int end   = rowp[w + 1];
    float edv = ed[w];

    // pass 1: denominator
    float den = 0.f;
    for (int base = start; base < end; base += 32) {
        int e = base + lane;
        float p = 0.f;
        if (e < end) {
            float x = es[csrc[e]] + edv;
            x = (x >= 0.f) ? x : 0.2f * x;
            p = __expf(x);
        }
        den += p;
    }
    #pragma unroll
    for (int o = 16; o; o >>= 1) den += __shfl_xor_sync(0xffffffffu, den, o);
    float inv = 1.f / den;

    // pass 2: weighted accumulation
    float acc[NH] = {};
    for (int base = start; base < end; base += 32) {
        int e = base + lane;
        int sl = 0;
        float p = 0.f;
        if (e < end) {
            sl = csrc[e];
            float x = es[sl] + edv;
            x = (x >= 0.f) ? x : 0.2f * x;
            p = __expf(x);
        }
        int cnt = min(32, end - base);
        for (int j = 0; j < cnt; j++) {
            int   s = __shfl_sync(0xffffffffu, sl, j);
            float a = __shfl_sync(0xffffffffu, p,  j) * inv;
            const __half* hp = h16 + (size_t)s * DIM + lane * NH;
            if (NH == 8) {
                uint4 raw = *reinterpret_cast<const uint4*>(hp);
                const __half2* hh = reinterpret_cast<const __half2*>(&raw);
                #pragma unroll
                for (int t = 0; t < 4; t++) {
                    float2 f = __half22float2(hh[t]);
                    acc[t * 2 + 0] += a * f.x;
                    acc[t * 2 + 1] += a * f.y;
                }
            } else {
                uint2 raw = *reinterpret_cast<const uint2*>(hp);
                const __half2* hh = reinterpret_cast<const __half2*>(&raw);
                #pragma unroll
                for (int t = 0; t < 2; t++) {
                    float2 f = __half22float2(hh[t]);
                    acc[t * 2 + 0] += a * f.x;
                    acc[t * 2 + 1] += a * f.y;
                }
            }
        }
    }

    // epilogue: bias (+relu), single vectorized write
    const float* bp = bias + lane * NH;
    float v[NH];
    #pragma unroll
    for (int t4 = 0; t4 < NH / 4; t4++) {
        float4 b = *reinterpret_cast<const float4*>(bp + t4 * 4);
        v[t4 * 4 + 0] = acc[t4 * 4 + 0] + b.x;
        v[t4 * 4 + 1] = acc[t4 * 4 + 1] + b.y;
        v[t4 * 4 + 2] = acc[t4 * 4 + 2] + b.z;
        v[t4 * 4 + 3] = acc[t4 * 4 + 3] + b.w;
    }
    if (RELU) {
        #pragma unroll
        for (int t = 0; t < NH; t++) v[t] = fmaxf(v[t], 0.f);
    }
    if (OUT16) {
        __half* op = outH + (size_t)w * DIM + lane * NH;
        __half2 hh[NH / 2];
        #pragma unroll
        for (int t = 0; t < NH / 2; t++) hh[t] = __floats2half2_rn(v[t * 2], v[t * 2 + 1]);
        if (NH == 8) *reinterpret_cast<uint4*>(op) = *reinterpret_cast<uint4*>(hh);
        else         *reinterpret_cast<uint2*>(op) = *reinterpret_cast<uint2*>(hh);
    } else {
        float* op = outF + (size_t)w * DIM + lane * NH;
        #pragma unroll
        for (int t4 = 0; t4 < NH / 4; t4++)
            *reinterpret_cast<float4*>(op + t4 * 4) =
                make_float4(v[t4 * 4 + 0], v[t4 * 4 + 1], v[t4 * 4 + 2], v[t4 * 4 + 3]);
    }
}

// ---------------------------------------------------------------
// link predictor (warp/pair, float4)
// ---------------------------------------------------------------
__global__ __launch_bounds__(256) void k_link_pred(
    const float* __restrict__ h, const int* __restrict__ mask,
    const float* __restrict__ Wl, const float* __restrict__ bl,
    float* __restrict__ out)
{
    int warp = (blockIdx.x * blockDim.x + threadIdx.x) >> 5;
    int lane = threadIdx.x & 31;
    if (warp >= PP) return;
    int m0 = mask[warp * 2 + 0];
    int m1 = mask[warp * 2 + 1];
    const float4* h0 = reinterpret_cast<const float4*>(h + (size_t)m0 * FIN);
    const float4* h1 = reinterpret_cast<const float4*>(h + (size_t)m1 * FIN);
    const float4* w0 = reinterpret_cast<const float4*>(Wl);
    const float4* w1 = reinterpret_cast<const float4*>(Wl + FIN);
    float4 a = h0[lane], wa = w0[lane];
    float4 b = h1[lane], wb = w1[lane];
    float acc = a.x * wa.x + a.y * wa.y + a.z * wa.z + a.w * wa.w
              + b.x * wb.x + b.y * wb.y + b.z * wb.z + b.w * wb.w;
    #pragma unroll
    for (int o = 16; o; o >>= 1) acc += __shfl_xor_sync(0xffffffffu, acc, o);
    if (lane == 0) out[warp] = 1.f / (1.f + __expf(-(acc + bl[0])));
}

// ---------------------------------------------------------------
extern "C" void kernel_launch(void* const* d_in, const int* in_sizes, int n_in,
                              void* d_out, int out_size)
{
    const float* features = (const float*)d_in[0];
    const int*   ei       = (const int*)  d_in[1];
    const int*   mask     = (const int*)  d_in[2];
    const float* W1       = (const float*)d_in[3];
    const float* a_src1   = (const float*)d_in[4];
    const float* a_dst1   = (const float*)d_in[5];
    const float* b1       = (const float*)d_in[6];
    const float* W2       = (const float*)d_in[7];
    const float* a_src2   = (const float*)d_in[8];
    const float* a_dst2   = (const float*)d_in[9];
    const float* b2       = (const float*)d_in[10];
    const float* Wl       = (const float*)d_in[11];
    const float* bl       = (const float*)d_in[12];
    float* out = (float*)d_out;

    __half *h1, *r16, *h2;
    float  *post, *es, *ed;
    int *deg, *rowp, *curs, *csrc;
    cudaGetSymbolAddress((void**)&h1,   g_h1);
    cudaGetSymbolAddress((void**)&r16,  g_r16);
    cudaGetSymbolAddress((void**)&h2,   g_h2);
    cudaGetSymbolAddress((void**)&post, g_post);
    cudaGetSymbolAddress((void**)&es,   g_es);
    cudaGetSymbolAddress((void**)&ed,   g_ed);
    cudaGetSymbolAddress((void**)&deg,  g_deg);
    cudaGetSymbolAddress((void**)&rowp, g_rowp);
    cudaGetSymbolAddress((void**)&curs, g_curs);
    cudaGetSymbolAddress((void**)&csrc, g_csrc);

    const int edgeBlocks     = (ETOT + 255) / 256;
    const int nodeWarpBlocks = (NN * 32 + 255) / 256;

    // ---- CSR build ----
    k_zero_deg  <<<(NN + 255) / 256, 256>>>(deg);
    k_hist      <<<edgeBlocks, 256>>>(ei, deg);
    k_scan_fused<<<1, SCAN_T>>>(deg, rowp, curs);
    k_scatter   <<<edgeBlocks, 256>>>(ei, curs, csrc);

    // ---- layer 1 ----
    {
        dim3 g(HH / BN, (NN + BM - 1) / BM);
        k_gemm_f16<true><<<g, 256>>>(features, W1, h1, NN, FIN, HH);
    }
    k_esed16<<<nodeWarpBlocks, 256>>>((const __half2*)h1, (const float2*)a_src1,
                                      (const float2*)a_dst1, es, ed, HH / 2);
    k_gat_agg<HH, true, true><<<nodeWarpBlocks, 256>>>(h1, es, ed, rowp, csrc, b1, nullptr, r16);

    // ---- layer 2 ----
    {
        dim3 g(FIN / BN, (NN + BM - 1) / BM);
        k_gemm_f16<false><<<g, 256>>>(r16, W2, h2, NN, HH, FIN);
    }
    k_esed16<<<nodeWarpBlocks, 256>>>((const __half2*)h2, (const float2*)a_src2,
                                      (const float2*)a_dst2, es, ed, FIN / 2);
    k_gat_agg<FIN, false, false><<<nodeWarpBlocks, 256>>>(h2, es, ed, rowp, csrc, b2, post, nullptr);

    // ---- link predictor ----
    k_link_pred<<<(PP * 32 + 255) / 256, 256>>>(post, mask, Wl, bl, out);
}